// round 6
// baseline (speedup 1.0000x reference)
#include <cuda_runtime.h>

__device__ __forceinline__ float4 vqc_one(float4 e0, float4 e1, float4 e2,
                                          float4 n0, float4 n1, float4 n2) {
    float t[12] = {e0.x, e0.y, e0.z, e0.w,
                   e1.x, e1.y, e1.z, e1.w,
                   e2.x, e2.y, e2.z, e2.w};
    float x[4], y[4], z[4];
#pragma unroll
    for (int q = 0; q < 4; q++) {
        float s0, c0, s1, c1, s2, c2;
        __sincosf(t[3 * q + 0], &s0, &c0);
        __sincosf(t[3 * q + 1], &s1, &c1);
        __sincosf(t[3 * q + 2], &s2, &c2);
        float cc = c0 * c1;
        x[q] = cc * c2 - s0 * s2;
        y[q] = cc * s2 + s0 * c2;
        z[q] = -c0 * s1;
    }
    float z01   = z[0] * z[1];
    float z23   = z[2] * z[3];
    float z012  = z01 * z[2];
    float z123  = z[1] * z23;
    float z0123 = z01 * z23;
    float x01   = x[0] * x[1];

    float4 o;
    o.x = n0.x * x01           + n0.y * (x[0] * y[1] * z23)         + n0.z * z123;
    o.y = n0.w * (x[1] * x[2]) + n1.x * (z[0] * y[1] * x[2])        + n1.y * z01;
    o.z = n1.z * (x[2] * x[3]) + n1.w * (z01 * y[2] * x[3])         + n2.x * z012;
    o.w = n2.y * (x01 * x[3])  - n2.z * (y[0] * y[1] * z[2] * y[3]) + n2.w * z0123;
    return o;
}

// 6 blocks/SM x 152 SMs = 912 blocks: exactly one resident wave, no tail churn.
__global__ __launch_bounds__(256, 6) void vqc_fused(const float4* __restrict__ enc,
                                                    const float* __restrict__ w,
                                                    float4* __restrict__ out,
                                                    int B) {
    // Per-block observable coefficients. Fast __sincosf: short prolog, no long
    // divergent slow path holding the whole block at the barrier.
    __shared__ __align__(16) float sn[12];
    if (threadIdx.x < 4) {
        int q = threadIdx.x;
        float th = w[q * 3 + 0];
        float lm = w[q * 3 + 2];
        float st, ct, sl, cl;
        __sincosf(th, &st, &ct);
        __sincosf(lm, &sl, &cl);
        sn[q * 3 + 0] = -st * cl;  // nx
        sn[q * 3 + 1] =  st * sl;  // ny
        sn[q * 3 + 2] =  ct;       // nz
    }
    __syncthreads();
    const float4* n4 = (const float4*)sn;
    float4 n0 = n4[0], n1 = n4[1], n2 = n4[2];

    const int stride = gridDim.x * blockDim.x;
    int i = blockIdx.x * blockDim.x + threadIdx.x;

    for (; i < B; i += stride) {
        const float4* p = enc + 3 * i;
        float4 e0 = __ldcs(p + 0);   // read-once stream
        float4 e1 = __ldcs(p + 1);
        float4 e2 = __ldcs(p + 2);
        float4 o = vqc_one(e0, e1, e2, n0, n1, n2);
        __stcs(&out[i], o);          // write-once stream
    }
}

extern "C" void kernel_launch(void* const* d_in, const int* in_sizes, int n_in,
                              void* d_out, int out_size) {
    int ei = 0, wi = 1;
    if (n_in >= 2 && in_sizes[0] < in_sizes[1]) { ei = 1; wi = 0; }
    const float* enc = (const float*)d_in[ei];
    const float* w   = (const float*)d_in[wi];
    int B = in_sizes[ei] / 12;

    const int threads = 256;
    // Exactly one resident wave at 6 blocks/SM (matches the 40-reg class).
    int max_blocks = 152 * 6;
    int need = (B + threads - 1) / threads;
    int blocks = need < max_blocks ? need : max_blocks;

    vqc_fused<<<blocks, threads>>>((const float4*)enc, w, (float4*)d_out, B);
}